// round 2
// baseline (speedup 1.0000x reference)
#include <cuda_runtime.h>
#include <math.h>

// BiLSTM: B=128, S=1024, D=128, H=256.
// Grid: 128 CTAs = dir(2) x btile(4, 32 batches) x hslice(16, 16 h).
// Each CTA: 64 rows (4 gates x 16 h) x 32 batches, K=384, 128 threads.
// Persistent kernel; per-step group barrier among the 16 h-slice CTAs of a
// (dir, btile) group; h state double-buffered in global memory.
// x tile for step s+1 is prefetched during the gate/barrier phase of step s.

#define S_LEN   1024
#define B_DIM   128
#define D_DIM   128
#define H_DIM   256
#define KCAT    384

// smem layout (floats)
#define W_OFF   0          // w_s[384][64]
#define X_OFF   24576      // x_s[128][32]
#define H_OFF   28672      // h_s[256][32]
#define Z_OFF   36864      // z_s[64][32]
#define C_OFF   38912      // c_s[16][32]
#define SMEM_FLOATS 39424
#define SMEM_BYTES  (SMEM_FLOATS * 4)

__device__ float g_hstate[2][2][B_DIM][H_DIM];  // [parity][dir][b][k]
__device__ unsigned int g_bar[8];

__global__ void reset_bar_kernel() {
    if (threadIdx.x < 8) g_bar[threadIdx.x] = 0u;
}

__device__ __forceinline__ float sigmoidf_fast(float x) {
    return 1.0f / (1.0f + __expf(-x));
}

__global__ void __launch_bounds__(128, 1)
bilstm_kernel(const float* __restrict__ x,
              const float* __restrict__ Wf, const float* __restrict__ bf,
              const float* __restrict__ Wb, const float* __restrict__ bb,
              float* __restrict__ out)
{
    extern __shared__ float smem[];
    float* w_s = smem + W_OFF;   // [k][64 rows]
    float* x_s = smem + X_OFF;   // [d][32 b]
    float* h_s = smem + H_OFF;   // [k][32 b]
    float* z_s = smem + Z_OFF;   // [64 rows][32 b]
    float* c_s = smem + C_OFF;   // [16 hh][32 b]

    const int tid = threadIdx.x;
    const int cta = blockIdx.x;          // 0..127
    const int dir = cta >> 6;            // 0..1
    const int bt  = (cta >> 4) & 3;      // 0..3
    const int ht  = cta & 15;            // 0..15
    const int grp = cta >> 4;            // dir*4 + bt, 0..7

    const float* W   = dir ? Wb : Wf;    // (4,256,384)
    const float* bia = dir ? bb : bf;    // (4,256)

    const int b_base = bt * 32;

    // ---- load weights once: w_s[k][r], r = g*16 + hh, h = ht*16 + hh ----
    for (int idx = tid; idx < KCAT * 64; idx += 128) {
        int k = idx % KCAT;
        int r = idx / KCAT;
        int g = r >> 4, hh = r & 15;
        w_s[k * 64 + r] = W[(g * 256 + ht * 16 + hh) * KCAT + k];
    }

    // thread tile: rows r0..r0+3 (single gate), cols b0..b0+3
    const int r0 = (tid >> 3) << 2;      // 0,4,...,60
    const int b0 = (tid & 7) << 2;       // 0,4,...,28
    const int g0  = r0 >> 4;
    const int hh0 = r0 & 15;
    float brg[4];
#pragma unroll
    for (int i = 0; i < 4; ++i)
        brg[i] = bia[g0 * 256 + ht * 16 + hh0 + i];

    // gate-math cell ownership: 4 cells per thread (same b, 4 consecutive hh)
    const int cb  = tid >> 2;            // 0..31 local batch
    const int chh = (tid & 3) << 2;      // 0,4,8,12

    for (int idx = tid; idx < 16 * 32; idx += 128) c_s[idx] = 0.0f;

    // ---- prime x tile for s = 0 ----
    {
        const int t0 = dir ? (S_LEN - 1) : 0;
        const float* xp = x + (size_t)t0 * 128 + b_base;
        for (int idx = tid; idx < 128 * 8; idx += 128) {
            int d = idx >> 3, b4 = idx & 7;
            float4 v = __ldg((const float4*)(xp + (size_t)d * (S_LEN * D_DIM)) + b4);
            ((float4*)(x_s + d * 32))[b4] = v;
        }
    }
    __syncthreads();

    for (int s = 0; s < S_LEN; ++s) {
        const int t = dir ? (S_LEN - 1 - s) : s;

        // ---- load h_s[k][b] from previous step (transpose on the fly) ----
        if (s == 0) {
            for (int idx = tid; idx < 256 * 32; idx += 128) h_s[idx] = 0.0f;
        } else {
            const float* hp = &g_hstate[(s - 1) & 1][dir][b_base][0];
            for (int idx = tid; idx < 32 * 64; idx += 128) {
                int b = idx >> 6, k4 = idx & 63;
                float4 v = __ldcg((const float4*)(hp + b * H_DIM) + k4);
                int k = k4 << 2;
                h_s[(k + 0) * 32 + b] = v.x;
                h_s[(k + 1) * 32 + b] = v.y;
                h_s[(k + 2) * 32 + b] = v.z;
                h_s[(k + 3) * 32 + b] = v.w;
            }
        }
        __syncthreads();

        // ---- GEMM: z[r][b] = bias + sum_k w_s[k][r] * concat[k][b] ----
        float acc[4][4];
#pragma unroll
        for (int i = 0; i < 4; ++i)
#pragma unroll
            for (int j = 0; j < 4; ++j) acc[i][j] = brg[i];

#pragma unroll 4
        for (int k = 0; k < D_DIM; ++k) {
            float4 wv = *(const float4*)(w_s + k * 64 + r0);
            float4 uv = *(const float4*)(x_s + k * 32 + b0);
            float wr[4] = {wv.x, wv.y, wv.z, wv.w};
            float ur[4] = {uv.x, uv.y, uv.z, uv.w};
#pragma unroll
            for (int i = 0; i < 4; ++i)
#pragma unroll
                for (int j = 0; j < 4; ++j) acc[i][j] += wr[i] * ur[j];
        }
#pragma unroll 4
        for (int k = 0; k < H_DIM; ++k) {
            float4 wv = *(const float4*)(w_s + (D_DIM + k) * 64 + r0);
            float4 uv = *(const float4*)(h_s + k * 32 + b0);
            float wr[4] = {wv.x, wv.y, wv.z, wv.w};
            float ur[4] = {uv.x, uv.y, uv.z, uv.w};
#pragma unroll
            for (int i = 0; i < 4; ++i)
#pragma unroll
                for (int j = 0; j < 4; ++j) acc[i][j] += wr[i] * ur[j];
        }

        // stage z for gate regrouping
#pragma unroll
        for (int i = 0; i < 4; ++i)
#pragma unroll
            for (int j = 0; j < 4; ++j)
                z_s[(r0 + i) * 32 + (b0 + j)] = acc[i][j];
        __syncthreads();

        // ---- prefetch x tile for step s+1 (x_s free after GEMM) ----
        if (s + 1 < S_LEN) {
            const int tn = dir ? (S_LEN - 2 - s) : (s + 1);
            const float* xp = x + (size_t)tn * 128 + b_base;
            for (int idx = tid; idx < 128 * 8; idx += 128) {
                int d = idx >> 3, b4 = idx & 7;
                float4 v = __ldg((const float4*)(xp + (size_t)d * (S_LEN * D_DIM)) + b4);
                ((float4*)(x_s + d * 32))[b4] = v;
            }
        }

        // ---- gates: f,i,c~,o ; c' = f*c + i*c~ ; h = o*tanh(c') ----
        float hv[4], cv[4];
#pragma unroll
        for (int i = 0; i < 4; ++i) {
            int hh = chh + i;
            float zf = z_s[(0 * 16 + hh) * 32 + cb];
            float zi = z_s[(1 * 16 + hh) * 32 + cb];
            float zc = z_s[(2 * 16 + hh) * 32 + cb];
            float zo = z_s[(3 * 16 + hh) * 32 + cb];
            float f  = sigmoidf_fast(zf);
            float ig = sigmoidf_fast(zi);
            float ct = tanhf(zc);
            float og = sigmoidf_fast(zo);
            float c  = f * c_s[hh * 32 + cb] + ig * ct;
            c_s[hh * 32 + cb] = c;
            hv[i] = og * tanhf(c);
            cv[i] = c;
        }

        const int b_glob = b_base + cb;
        const int h_glob = ht * 16 + chh;
        float4 hv4 = make_float4(hv[0], hv[1], hv[2], hv[3]);

        // h state (for step s+1), parity s&1
        *(float4*)(&g_hstate[s & 1][dir][b_glob][h_glob]) = hv4;

        // output: (B, S, 2H)
        *(float4*)(out + ((size_t)b_glob * S_LEN + t) * (2 * H_DIM)
                       + dir * H_DIM + h_glob) = hv4;

        if (s == S_LEN - 1) {
            size_t base = (size_t)B_DIM * S_LEN * 2 * H_DIM;
            size_t off  = ((size_t)dir * B_DIM + b_glob) * H_DIM + h_glob;
            *(float4*)(out + base + off) = hv4;
            *(float4*)(out + base + 2u * B_DIM * H_DIM + off) =
                make_float4(cv[0], cv[1], cv[2], cv[3]);
        }

        // ---- group barrier: 16 CTAs of (dir, btile) ----
        __syncthreads();
        if (tid == 0) {
            __threadfence();
            atomicAdd(&g_bar[grp], 1u);
            unsigned tgt = 16u * (unsigned)(s + 1);
            volatile unsigned* p = (volatile unsigned*)&g_bar[grp];
            while (*p < tgt) { __nanosleep(40); }
            __threadfence();
        }
        __syncthreads();
    }
}

extern "C" void kernel_launch(void* const* d_in, const int* in_sizes, int n_in,
                              void* d_out, int out_size) {
    const float* x  = (const float*)d_in[0];
    const float* Wf = (const float*)d_in[1];
    const float* bf = (const float*)d_in[2];
    const float* Wb = (const float*)d_in[3];
    const float* bb = (const float*)d_in[4];
    float* out = (float*)d_out;

    cudaFuncSetAttribute(bilstm_kernel,
                         cudaFuncAttributeMaxDynamicSharedMemorySize,
                         SMEM_BYTES);

    reset_bar_kernel<<<1, 32>>>();
    bilstm_kernel<<<128, 128, SMEM_BYTES>>>(x, Wf, bf, Wb, bb, out);
}